// round 14
// baseline (speedup 1.0000x reference)
#include <cuda_runtime.h>
#include <cuda_bf16.h>
#include <cstdint>

// Problem dims (fixed by the dataset)
#define B_  64
#define T_  256
#define D_  512
#define H_  1024
#define M_  (B_ * T_)   // 16384
#define MT_ (M_ / 2)    // 8192 rows handled by the tensor half

#define TBK 32          // tensor path: bf16 per k-tile (64 B per row)

// ---------------------------------------------------------------------------
// Scratch (__device__ globals; no allocations anywhere)
// ---------------------------------------------------------------------------
__device__ __nv_bfloat16 g_xs[3][(size_t)MT_ * D_];  // x splits (rows 0..8191), 24 MB
__device__ __nv_bfloat16 g_ws[3][(size_t)H_ * D_];   // W_in splits, 3 MB
__device__ float g_pre[(size_t)M_ * H_];             // 64 MB pre-activations
__device__ float g_part[256];

// ---------------------------------------------------------------------------
// Helpers (baseline-target PTX: cp.async / ldmatrix / mma.sync / named bar)
// ---------------------------------------------------------------------------
__device__ __forceinline__ uint32_t smem_u32(const void* p) {
    uint32_t a;
    asm("{ .reg .u64 t; cvta.to.shared.u64 t, %1; cvt.u32.u64 %0, t; }"
        : "=r"(a) : "l"(p));
    return a;
}
__device__ __forceinline__ void cp_async16(uint32_t dst, const void* src) {
    asm volatile(
        "{ .reg .u64 g; cvta.to.global.u64 g, %1; "
        "cp.async.cg.shared.global [%0], [g], 16; }"
        :: "r"(dst), "l"(src) : "memory");
}
#define CP_COMMIT() asm volatile("cp.async.commit_group;" ::: "memory")
#define CP_WAIT0()  asm volatile("cp.async.wait_group 0;" ::: "memory")
#define BAR(id)     asm volatile("bar.sync %0, 256;" :: "r"(id) : "memory")

// ---------------------------------------------------------------------------
// Kernel 0: 3-way bf16 split (hi+mid+lo) of x rows 0..8191 / all of W_in
// ---------------------------------------------------------------------------
__device__ __forceinline__ void split3(float x, __nv_bfloat16& h, __nv_bfloat16& m,
                                       __nv_bfloat16& l) {
    h = __float2bfloat16_rn(x);
    float r = x - __bfloat162float(h);
    m = __float2bfloat16_rn(r);
    float r2 = r - __bfloat162float(m);
    l = __float2bfloat16_rn(r2);
}

__global__ __launch_bounds__(256) void split_kernel(const float* __restrict__ src, int mode) {
    size_t i = ((size_t)blockIdx.x * blockDim.x + threadIdx.x) * 4;
    float4 v = *(const float4*)(src + i);
    __align__(8) __nv_bfloat16 h[4], m[4], l[4];
    split3(v.x, h[0], m[0], l[0]);
    split3(v.y, h[1], m[1], l[1]);
    split3(v.z, h[2], m[2], l[2]);
    split3(v.w, h[3], m[3], l[3]);
    if (mode == 0) {
        *(uint2*)&g_xs[0][i] = *(uint2*)h;
        *(uint2*)&g_xs[1][i] = *(uint2*)m;
        *(uint2*)&g_xs[2][i] = *(uint2*)l;
    } else {
        *(uint2*)&g_ws[0][i] = *(uint2*)h;
        *(uint2*)&g_ws[1][i] = *(uint2*)m;
        *(uint2*)&g_ws[2][i] = *(uint2*)l;
    }
}

// ---------------------------------------------------------------------------
// Hybrid GEMM kernel, 512 threads, 1 CTA/SM.
//   warps 0-7  (threadIdx < 256): FFMA2 SGEMM (R8 config, bitwise == scalar)
//                                 on M rows 8192..16383
//   warps 8-15 (threadIdx >= 256): 6-pass bf16 mma.sync split GEMM (R5 code)
//                                 on M rows 0..8191
// The halves are independent; each uses its own named barrier (1 / 2) so the
// two pipelines' k-tile cadences never couple. Both use the fma / tensor
// pipes respectively -> concurrent utilization of both.
// Dynamic smem pool layout:
//   [0, 8K)      F_sA [2][8][128] f32       [8K, 16K)  F_sB
//   [16K, 32K)   T_sA [2][128*32] bf16      [32K, 48K) T_sB
//   [48K, 48.5K) tensor-half bias cache
// ---------------------------------------------------------------------------
#define POOL_BYTES (49152 + 512)

__global__ __launch_bounds__(512, 1) void gemm_hybrid_kernel(
    const float* __restrict__ A,
    const float* __restrict__ W,
    const float* __restrict__ bias)
{
    extern __shared__ __align__(16) char pool[];
    float* F_sA = (float*)pool;               // [2][8][128]
    float* F_sB = (float*)(pool + 8192);      // [2][8][128]
    char*  T_sA = pool + 16384;               // bf16 [2][128*TBK]
    char*  T_sB = pool + 32768;
    float* s_biasT = (float*)(pool + 49152);  // [128]

    const int ntile = blockIdx.x;             // 0..7
    const int mtile = blockIdx.y;             // 0..63
    const int bn = ntile * 128;

    if (threadIdx.x < 256) {
        // ================= FFMA half: rows 8192 + mtile*128 =================
        const int tid = threadIdx.x;
        const int bm = MT_ + mtile * 128;

        const int lrow = tid >> 1;
        const int lcol = (tid & 1) * 4;
        const float* Ap = A + (size_t)(bm + lrow) * D_ + lcol;
        const float* Wp = W + (size_t)(bn + lrow) * D_ + lcol;

#define FSA(b, k, i) F_sA[((b) << 10) + ((k) << 7) + (i)]
#define FSB(b, k, i) F_sB[((b) << 10) + ((k) << 7) + (i)]

        {
            float4 a4 = *(const float4*)Ap;
            float4 w4 = *(const float4*)Wp;
            FSA(0, lcol + 0, lrow) = a4.x; FSA(0, lcol + 1, lrow) = a4.y;
            FSA(0, lcol + 2, lrow) = a4.z; FSA(0, lcol + 3, lrow) = a4.w;
            FSB(0, lcol + 0, lrow) = w4.x; FSB(0, lcol + 1, lrow) = w4.y;
            FSB(0, lcol + 2, lrow) = w4.z; FSB(0, lcol + 3, lrow) = w4.w;
        }
        BAR(1);

        const int tx = tid & 15;
        const int ty = tid >> 4;

        unsigned long long acc2[8][4];
#pragma unroll
        for (int i = 0; i < 8; i++)
#pragma unroll
            for (int jp = 0; jp < 4; jp++) acc2[i][jp] = 0ull;

        int buf = 0;
        for (int k0 = 8; k0 <= D_; k0 += 8) {
            const bool more = (k0 < D_);
            float4 na, nw;
            if (more) {
                na = *(const float4*)(Ap + k0);
                nw = *(const float4*)(Wp + k0);
            }
#pragma unroll
            for (int kk = 0; kk < 8; kk++) {
                float ra[8];
                unsigned long long rb2[4];
                *(float4*)&ra[0] = *(const float4*)&FSA(buf, kk, ty * 4);
                *(float4*)&ra[4] = *(const float4*)&FSA(buf, kk, 64 + ty * 4);
                *(ulonglong2*)&rb2[0] = *(const ulonglong2*)&FSB(buf, kk, tx * 4);
                *(ulonglong2*)&rb2[2] = *(const ulonglong2*)&FSB(buf, kk, 64 + tx * 4);
#pragma unroll
                for (int i = 0; i < 8; i++) {
                    unsigned long long a2;
                    asm("mov.b64 %0, {%1, %1};" : "=l"(a2) : "f"(ra[i]));
#pragma unroll
                    for (int jp = 0; jp < 4; jp++) {
                        asm("fma.rn.f32x2 %0, %1, %2, %0;"
                            : "+l"(acc2[i][jp])
                            : "l"(a2), "l"(rb2[jp]));
                    }
                }
            }
            if (more) {
                buf ^= 1;
                FSA(buf, lcol + 0, lrow) = na.x; FSA(buf, lcol + 1, lrow) = na.y;
                FSA(buf, lcol + 2, lrow) = na.z; FSA(buf, lcol + 3, lrow) = na.w;
                FSB(buf, lcol + 0, lrow) = nw.x; FSB(buf, lcol + 1, lrow) = nw.y;
                FSB(buf, lcol + 2, lrow) = nw.z; FSB(buf, lcol + 3, lrow) = nw.w;
                BAR(1);
            }
        }

        float acc[8][8];
#pragma unroll
        for (int i = 0; i < 8; i++)
#pragma unroll
            for (int jp = 0; jp < 4; jp++) {
                acc[i][2 * jp + 0] = __uint_as_float((uint32_t)(acc2[i][jp]));
                acc[i][2 * jp + 1] = __uint_as_float((uint32_t)(acc2[i][jp] >> 32));
            }

        float bs[8];
#pragma unroll
        for (int j = 0; j < 8; j++) {
            int n = bn + ((j < 4) ? (tx * 4 + j) : (64 + tx * 4 + (j - 4)));
            bs[j] = bias[n];
        }
#pragma unroll
        for (int i = 0; i < 8; i++) {
            int m = bm + ((i < 4) ? (ty * 4 + i) : (64 + ty * 4 + (i - 4)));
            float4 v0 = make_float4(acc[i][0] + bs[0], acc[i][1] + bs[1],
                                    acc[i][2] + bs[2], acc[i][3] + bs[3]);
            float4 v1 = make_float4(acc[i][4] + bs[4], acc[i][5] + bs[5],
                                    acc[i][6] + bs[6], acc[i][7] + bs[7]);
            *(float4*)&g_pre[(size_t)m * H_ + bn + tx * 4] = v0;
            *(float4*)&g_pre[(size_t)m * H_ + bn + 64 + tx * 4] = v1;
        }
    } else {
        // ============ Tensor half: rows mtile*128 (0..8191), 6-pass ============
        const int t2   = threadIdx.x - 256;   // 0..255
        const int lane = t2 & 31;
        const int w2   = t2 >> 5;             // 0..7
        const int wm   = (w2 >> 2) * 64;
        const int wn   = (w2 & 3) * 32;
        const int bm   = mtile * 128;

        if (t2 < 128) s_biasT[t2] = bias[bn + t2];

        const uint32_t uA0 = smem_u32(T_sA);
        const uint32_t uA1 = smem_u32(T_sA + 8192);
        const uint32_t uB0 = smem_u32(T_sB);
        const uint32_t uB1 = smem_u32(T_sB + 8192);

        const int r0 = t2 >> 2;               // 0..63
        const int c0 = t2 & 3;
        const int rA1 = r0 + 64;
        const uint32_t dOff0 = (uint32_t)r0  * 64u + (uint32_t)((c0 ^ (r0  & 3)) << 4);
        const uint32_t dOff1 = (uint32_t)rA1 * 64u + (uint32_t)((c0 ^ (rA1 & 3)) << 4);
        const int gcol = c0 * 8;

        float acc[4][4][4];
#pragma unroll
        for (int i = 0; i < 4; i++)
#pragma unroll
            for (int j = 0; j < 4; j++)
#pragma unroll
                for (int k = 0; k < 4; k++) acc[i][j][k] = 0.0f;

        const int baseRowA = wm + (lane & 7) + ((lane >> 3) & 1) * 8;
        const int chA_s0 = (lane >> 4) ^ (lane & 3);
        const int chA_s1 = (2 + (lane >> 4)) ^ (lane & 3);
        const int baseRowB = wn + (lane & 7);
        const int chB_s0 = ((lane >> 3) & 1) ^ (lane & 3);
        const int chB_s1 = (2 + ((lane >> 3) & 1)) ^ (lane & 3);

        auto issue_tile = [&](int seg, int it, uint32_t ua, uint32_t ub) {
            const __nv_bfloat16* Ab =
                (seg == 2 || seg == 4) ? g_xs[1] : (seg == 5 ? g_xs[2] : g_xs[0]);
            const __nv_bfloat16* Bb =
                (seg == 1 || seg == 4) ? g_ws[1] : (seg == 3 ? g_ws[2] : g_ws[0]);
            const int k0 = it * TBK + gcol;
            cp_async16(ua + dOff0, Ab + (size_t)(bm + r0)  * D_ + k0);
            cp_async16(ua + dOff1, Ab + (size_t)(bm + rA1) * D_ + k0);
            cp_async16(ub + dOff0, Bb + (size_t)(bn + r0)  * D_ + k0);
            cp_async16(ub + dOff1, Bb + (size_t)(bn + rA1) * D_ + k0);
        };

        auto compute = [&](uint32_t ua, uint32_t ub) {
#pragma unroll
            for (int step = 0; step < 2; ++step) {
                const int chA = step ? chA_s1 : chA_s0;
                const int chB = step ? chB_s1 : chB_s0;
                uint32_t a[4][4], b[4][2];
#pragma unroll
                for (int mi = 0; mi < 4; ++mi) {
                    uint32_t addr = ua + (uint32_t)(baseRowA + mi * 16) * 64u
                                       + ((uint32_t)chA << 4);
                    asm volatile(
                        "ldmatrix.sync.aligned.m8n8.x4.shared.b16 {%0,%1,%2,%3}, [%4];"
                        : "=r"(a[mi][0]), "=r"(a[mi][1]), "=r"(a[mi][2]), "=r"(a[mi][3])
                        : "r"(addr));
                }
#pragma unroll
                for (int ni = 0; ni < 4; ++ni) {
                    uint32_t addr = ub + (uint32_t)(baseRowB + ni * 8) * 64u
                                       + ((uint32_t)chB << 4);
                    asm volatile(
                        "ldmatrix.sync.aligned.m8n8.x2.shared.b16 {%0,%1}, [%2];"
                        : "=r"(b[ni][0]), "=r"(b[ni][1])
                        : "r"(addr));
                }
#pragma unroll
                for (int mi = 0; mi < 4; ++mi)
#pragma unroll
                    for (int ni = 0; ni < 4; ++ni)
                        asm volatile(
                            "mma.sync.aligned.m16n8k16.row.col.f32.bf16.bf16.f32 "
                            "{%0,%1,%2,%3}, {%4,%5,%6,%7}, {%8,%9}, {%0,%1,%2,%3};"
                            : "+f"(acc[mi][ni][0]), "+f"(acc[mi][ni][1]),
                              "+f"(acc[mi][ni][2]), "+f"(acc[mi][ni][3])
                            : "r"(a[mi][0]), "r"(a[mi][1]), "r"(a[mi][2]), "r"(a[mi][3]),
                              "r"(b[ni][0]), "r"(b[ni][1]));
            }
        };

        issue_tile(0, 0, uA0, uB0);
        CP_COMMIT();
        CP_WAIT0();
        BAR(2);

        int buf = 0;
        for (int ks = 0; ks < 96; ++ks) {
            if (ks + 1 < 96) {
                const int nx = ks + 1;
                issue_tile(nx >> 4, nx & 15, buf ? uA0 : uA1, buf ? uB0 : uB1);
            }
            CP_COMMIT();
            compute(buf ? uA1 : uA0, buf ? uB1 : uB0);
            CP_WAIT0();
            BAR(2);
            buf ^= 1;
        }

        const int mrow = lane >> 2;
        const int ncol = (lane & 3) * 2;
#pragma unroll
        for (int mi = 0; mi < 4; ++mi) {
            const int m0 = bm + wm + mi * 16 + mrow;
#pragma unroll
            for (int ni = 0; ni < 4; ++ni) {
                const int nc = wn + ni * 8 + ncol;
                const int n0 = bn + nc;
                float2 v0 = make_float2(acc[mi][ni][0] + s_biasT[nc],
                                        acc[mi][ni][1] + s_biasT[nc + 1]);
                float2 v1 = make_float2(acc[mi][ni][2] + s_biasT[nc],
                                        acc[mi][ni][3] + s_biasT[nc + 1]);
                *(float2*)&g_pre[(size_t)m0 * H_ + n0] = v0;
                *(float2*)&g_pre[(size_t)(m0 + 8) * H_ + n0] = v1;
            }
        }
    }
}

// ---------------------------------------------------------------------------
// Kernel 2: ALIF recurrence (16-deep MLP batches) + weighted partial reduce
// ---------------------------------------------------------------------------
__global__ __launch_bounds__(256) void alif_scan_kernel(
    const float* __restrict__ W_out)
{
    const int b  = blockIdx.x >> 2;
    const int hc = blockIdx.x & 3;
    const int h  = hc * 256 + threadIdx.x;

    const float* p = g_pre + (size_t)b * T_ * H_ + h;

    float mem = 0.0f, adapt = 0.0f, cnt = 0.0f;

    for (int t0 = 0; t0 < T_; t0 += 16) {
        float v[16];
#pragma unroll
        for (int q = 0; q < 16; q++)
            v[q] = p[(size_t)(t0 + q) * H_];
#pragma unroll
        for (int q = 0; q < 16; q++) {
            mem = 0.9f * mem + v[q] - adapt;
            float spk = (mem > 0.0f) ? 1.0f : 0.0f;
            adapt += 0.1f * spk;
            mem -= spk;
            cnt += spk;
        }
    }

    float val = cnt * (1.0f / (float)T_) * W_out[h];

    __shared__ float red[256];
    red[threadIdx.x] = val;
    __syncthreads();
#pragma unroll
    for (int s = 128; s > 0; s >>= 1) {
        if (threadIdx.x < s) red[threadIdx.x] += red[threadIdx.x + s];
        __syncthreads();
    }
    if (threadIdx.x == 0) g_part[blockIdx.x] = red[0];
}

__global__ void finalize_kernel(const float* __restrict__ b_out,
                                float* __restrict__ out)
{
    int b = threadIdx.x;
    if (b < B_) {
        float s = g_part[b * 4 + 0] + g_part[b * 4 + 1] +
                  g_part[b * 4 + 2] + g_part[b * 4 + 3];
        out[b] = s + b_out[0];
    }
}

extern "C" void kernel_launch(void* const* d_in, const int* in_sizes, int n_in,
                              void* d_out, int out_size)
{
    (void)in_sizes; (void)n_in; (void)out_size;
    const float* x     = (const float*)d_in[0];  // [64,256,512]
    const float* W_in  = (const float*)d_in[1];  // [1024,512]
    const float* b_in  = (const float*)d_in[2];  // [1024]
    const float* W_out = (const float*)d_in[3];  // [1,1024]
    const float* b_out = (const float*)d_in[4];  // [1]
    float* out = (float*)d_out;                  // [64,1]

    cudaFuncSetAttribute(gemm_hybrid_kernel,
                         cudaFuncAttributeMaxDynamicSharedMemorySize, POOL_BYTES);

    // Split only the tensor half's x rows (0..8191) + all of W
    split_kernel<<<(MT_ * D_) / 4 / 256, 256>>>(x, 0);
    split_kernel<<<(H_ * D_) / 4 / 256, 256>>>(W_in, 1);

    dim3 ggrid(H_ / 128, M_ / 256);              // (8, 64) = 512 blocks
    gemm_hybrid_kernel<<<ggrid, 512, POOL_BYTES>>>(x, W_in, b_in);

    alif_scan_kernel<<<256, 256>>>(W_out);
    finalize_kernel<<<1, 64>>>(b_out, out);
}

// round 16
// speedup vs baseline: 1.1554x; 1.1554x over previous
#include <cuda_runtime.h>
#include <cstdint>

// Problem dims (fixed by the dataset)
#define B_  64
#define T_  256
#define D_  512
#define H_  1024
#define M_  (B_ * T_)   // 16384

// GEMM tiling
#define BM 128
#define BN 128
#define BK 8

// Scratch (allocation-free rule: __device__ globals; zero-initialized at load)
__device__ float g_pre[(size_t)M_ * H_];   // 64 MB: pre-activations
__device__ float g_part[256];
__device__ int   g_cnt[B_];                // per-batch completed-tile counters

// ---------------------------------------------------------------------------
// Fused kernel: GEMM tile (R12 config, frozen/bitwise) + in-kernel ALIF scan.
//   Phase 1 (all 1024 blocks): g_pre[m,n] = sum_k A[m,k]*W[n,k] + bias[n]
//     for tile (ntile, mtile); publish completion to g_cnt[mtile>>1].
//   Phase 2 (blocks with ntile < 2): scan unit u = 2*mtile + ntile,
//     b = u>>2, hc = u&3; poll g_cnt[b]==16, then run the T-recurrence for
//     h in [hc*256, hc*256+256) and reduce into g_part[u].
// ---------------------------------------------------------------------------
__global__ __launch_bounds__(256, 2) void gemm_scan_kernel(
    const float* __restrict__ A,
    const float* __restrict__ W,
    const float* __restrict__ bias,
    const float* __restrict__ W_out)
{
    __shared__ float sA[2][BK][BM];
    __shared__ float sB[2][BK][BN];

    const int tid = threadIdx.x;
    const int ntile = blockIdx.x;     // 0..7
    const int mtile = blockIdx.y;     // 0..127
    const int bm = mtile * BM;
    const int bn = ntile * BN;

    // ---------------- Phase 1: GEMM (identical to R12 best) ----------------
    {
        const int lrow = tid >> 1;        // 0..127
        const int lcol = (tid & 1) * 4;   // 0 or 4
        const float* Ap = A + (size_t)(bm + lrow) * D_ + lcol;
        const float* Wp = W + (size_t)(bn + lrow) * D_ + lcol;

        {
            float4 a4 = *(const float4*)Ap;
            float4 w4 = *(const float4*)Wp;
            sA[0][lcol + 0][lrow] = a4.x; sA[0][lcol + 1][lrow] = a4.y;
            sA[0][lcol + 2][lrow] = a4.z; sA[0][lcol + 3][lrow] = a4.w;
            sB[0][lcol + 0][lrow] = w4.x; sB[0][lcol + 1][lrow] = w4.y;
            sB[0][lcol + 2][lrow] = w4.z; sB[0][lcol + 3][lrow] = w4.w;
        }
        __syncthreads();

        const int tx = tid & 15;
        const int ty = tid >> 4;

        unsigned long long acc2[8][4];
#pragma unroll
        for (int i = 0; i < 8; i++)
#pragma unroll
            for (int jp = 0; jp < 4; jp++) acc2[i][jp] = 0ull;

        int buf = 0;
        for (int k0 = BK; k0 <= D_; k0 += BK) {
            const bool more = (k0 < D_);
            float4 na, nw;
            if (more) {
                na = *(const float4*)(Ap + k0);
                nw = *(const float4*)(Wp + k0);
            }
#pragma unroll
            for (int kk = 0; kk < BK; kk++) {
                float ra[8];
                unsigned long long rb2[4];
                *(float4*)&ra[0] = *(const float4*)&sA[buf][kk][ty * 4];
                *(float4*)&ra[4] = *(const float4*)&sA[buf][kk][64 + ty * 4];
                *(ulonglong2*)&rb2[0] = *(const ulonglong2*)&sB[buf][kk][tx * 4];
                *(ulonglong2*)&rb2[2] = *(const ulonglong2*)&sB[buf][kk][64 + tx * 4];
#pragma unroll
                for (int i = 0; i < 8; i++) {
                    unsigned long long a2;
                    asm("mov.b64 %0, {%1, %1};" : "=l"(a2) : "f"(ra[i]));
#pragma unroll
                    for (int jp = 0; jp < 4; jp++) {
                        asm("fma.rn.f32x2 %0, %1, %2, %0;"
                            : "+l"(acc2[i][jp])
                            : "l"(a2), "l"(rb2[jp]));
                    }
                }
            }
            if (more) {
                buf ^= 1;
                sA[buf][lcol + 0][lrow] = na.x; sA[buf][lcol + 1][lrow] = na.y;
                sA[buf][lcol + 2][lrow] = na.z; sA[buf][lcol + 3][lrow] = na.w;
                sB[buf][lcol + 0][lrow] = nw.x; sB[buf][lcol + 1][lrow] = nw.y;
                sB[buf][lcol + 2][lrow] = nw.z; sB[buf][lcol + 3][lrow] = nw.w;
                __syncthreads();
            }
        }

        float acc[8][8];
#pragma unroll
        for (int i = 0; i < 8; i++)
#pragma unroll
            for (int jp = 0; jp < 4; jp++) {
                acc[i][2 * jp + 0] = __uint_as_float((uint32_t)(acc2[i][jp]));
                acc[i][2 * jp + 1] = __uint_as_float((uint32_t)(acc2[i][jp] >> 32));
            }

        float bs[8];
#pragma unroll
        for (int j = 0; j < 8; j++) {
            int n = bn + ((j < 4) ? (tx * 4 + j) : (64 + tx * 4 + (j - 4)));
            bs[j] = bias[n];
        }
#pragma unroll
        for (int i = 0; i < 8; i++) {
            int m = bm + ((i < 4) ? (ty * 4 + i) : (64 + ty * 4 + (i - 4)));
            float4 v0 = make_float4(acc[i][0] + bs[0], acc[i][1] + bs[1],
                                    acc[i][2] + bs[2], acc[i][3] + bs[3]);
            float4 v1 = make_float4(acc[i][4] + bs[4], acc[i][5] + bs[5],
                                    acc[i][6] + bs[6], acc[i][7] + bs[7]);
            *(float4*)&g_pre[(size_t)m * H_ + bn + tx * 4] = v0;
            *(float4*)&g_pre[(size_t)m * H_ + bn + 64 + tx * 4] = v1;
        }
    }

    // Publish this tile: all stores visible, then bump the batch counter.
    __threadfence();
    __syncthreads();
    if (tid == 0) atomicAdd(&g_cnt[mtile >> 1], 1);

    // ---------------- Phase 2: scan (blocks with ntile < 2) ----------------
    if (ntile < 2) {
        const int u  = mtile * 2 + ntile;   // 0..255
        const int b  = u >> 2;
        const int hc = u & 3;

        if (tid == 0) {
            while (atomicAdd(&g_cnt[b], 0) < 16)
                __nanosleep(64);
        }
        __syncthreads();
        __threadfence();   // acquire: order polled flag before data reads

        const int h = hc * 256 + tid;
        const float* p = g_pre + (size_t)b * T_ * H_ + h;

        float mem = 0.0f, adapt = 0.0f, cnt = 0.0f;
        for (int t0 = 0; t0 < T_; t0 += 16) {
            float v[16];
#pragma unroll
            for (int q = 0; q < 16; q++)
                v[q] = __ldcg(p + (size_t)(t0 + q) * H_);   // L2-coherent loads
#pragma unroll
            for (int q = 0; q < 16; q++) {
                mem = 0.9f * mem + v[q] - adapt;
                float spk = (mem > 0.0f) ? 1.0f : 0.0f;
                adapt += 0.1f * spk;
                mem -= spk;
                cnt += spk;
            }
        }

        float val = cnt * (1.0f / (float)T_) * W_out[h];

        __shared__ float red[256];
        red[tid] = val;
        __syncthreads();
#pragma unroll
        for (int s = 128; s > 0; s >>= 1) {
            if (tid < s) red[tid] += red[tid + s];
            __syncthreads();
        }
        if (tid == 0) g_part[u] = red[0];
    }
}

// ---------------------------------------------------------------------------
// Finalize: out[b] = sum_c g_part[b*4+c] + b_out[0]; also resets g_cnt so the
// next graph replay starts from a clean state (globals are zero-init once).
// ---------------------------------------------------------------------------
__global__ void finalize_kernel(const float* __restrict__ b_out,
                                float* __restrict__ out)
{
    int b = threadIdx.x;
    if (b < B_) {
        float s = g_part[b * 4 + 0] + g_part[b * 4 + 1] +
                  g_part[b * 4 + 2] + g_part[b * 4 + 3];
        out[b] = s + b_out[0];
        g_cnt[b] = 0;
    }
}

extern "C" void kernel_launch(void* const* d_in, const int* in_sizes, int n_in,
                              void* d_out, int out_size)
{
    (void)in_sizes; (void)n_in; (void)out_size;
    const float* x     = (const float*)d_in[0];  // [64,256,512]
    const float* W_in  = (const float*)d_in[1];  // [1024,512]
    const float* b_in  = (const float*)d_in[2];  // [1024]
    const float* W_out = (const float*)d_in[3];  // [1,1024]
    const float* b_out = (const float*)d_in[4];  // [1]
    float* out = (float*)d_out;                  // [64,1]

    dim3 ggrid(H_ / BN, M_ / BM);                // (8, 128)
    gemm_scan_kernel<<<ggrid, 256>>>(x, W_in, b_in, W_out);
    finalize_kernel<<<1, 64>>>(b_out, out);
}

// round 17
// speedup vs baseline: 1.2333x; 1.0675x over previous
#include <cuda_runtime.h>
#include <cstdint>

// Problem dims (fixed by the dataset)
#define B_  64
#define T_  256
#define D_  512
#define H_  1024
#define M_  (B_ * T_)   // 16384

// GEMM tiling
#define BM 128
#define BN 128
#define BK 8

// Scratch (allocation-free rule: __device__ globals; zero-initialized at load)
__device__ float g_pre[(size_t)M_ * H_];   // 64 MB: pre-activations
__device__ float g_part[256];
__device__ int   g_ticket;                 // scan-completion ticket

// ---------------------------------------------------------------------------
// Kernel 1: g_pre[m,n] = sum_k A[m,k] * W[n,k] + bias[n]
// 128x128x8 double-buffered SGEMM, 256 threads, 8x8 per-thread tile with 4+4
// split fragments; n-paired fma.rn.f32x2 (FFMA2), per-component ascending-k
// chain => bitwise identical to scalar FFMA. (Frozen R12 configuration.)
// ---------------------------------------------------------------------------
__global__ __launch_bounds__(256, 2) void gemm_bias_kernel(
    const float* __restrict__ A,
    const float* __restrict__ W,
    const float* __restrict__ bias)
{
    __shared__ float sA[2][BK][BM];
    __shared__ float sB[2][BK][BN];

    const int tid = threadIdx.x;
    const int bm = blockIdx.y * BM;
    const int bn = blockIdx.x * BN;

    const int lrow = tid >> 1;        // 0..127
    const int lcol = (tid & 1) * 4;   // 0 or 4
    const float* Ap = A + (size_t)(bm + lrow) * D_ + lcol;
    const float* Wp = W + (size_t)(bn + lrow) * D_ + lcol;

    {
        float4 a4 = *(const float4*)Ap;
        float4 w4 = *(const float4*)Wp;
        sA[0][lcol + 0][lrow] = a4.x; sA[0][lcol + 1][lrow] = a4.y;
        sA[0][lcol + 2][lrow] = a4.z; sA[0][lcol + 3][lrow] = a4.w;
        sB[0][lcol + 0][lrow] = w4.x; sB[0][lcol + 1][lrow] = w4.y;
        sB[0][lcol + 2][lrow] = w4.z; sB[0][lcol + 3][lrow] = w4.w;
    }
    __syncthreads();

    const int tx = tid & 15;   // n-direction
    const int ty = tid >> 4;   // m-direction

    unsigned long long acc2[8][4];
#pragma unroll
    for (int i = 0; i < 8; i++)
#pragma unroll
        for (int jp = 0; jp < 4; jp++) acc2[i][jp] = 0ull;

    int buf = 0;
    for (int k0 = BK; k0 <= D_; k0 += BK) {
        const bool more = (k0 < D_);
        float4 na, nw;
        if (more) {
            na = *(const float4*)(Ap + k0);
            nw = *(const float4*)(Wp + k0);
        }
#pragma unroll
        for (int kk = 0; kk < BK; kk++) {
            float ra[8];
            unsigned long long rb2[4];
            *(float4*)&ra[0] = *(const float4*)&sA[buf][kk][ty * 4];
            *(float4*)&ra[4] = *(const float4*)&sA[buf][kk][64 + ty * 4];
            *(ulonglong2*)&rb2[0] = *(const ulonglong2*)&sB[buf][kk][tx * 4];
            *(ulonglong2*)&rb2[2] = *(const ulonglong2*)&sB[buf][kk][64 + tx * 4];
#pragma unroll
            for (int i = 0; i < 8; i++) {
                unsigned long long a2;
                asm("mov.b64 %0, {%1, %1};" : "=l"(a2) : "f"(ra[i]));
#pragma unroll
                for (int jp = 0; jp < 4; jp++) {
                    asm("fma.rn.f32x2 %0, %1, %2, %0;"
                        : "+l"(acc2[i][jp])
                        : "l"(a2), "l"(rb2[jp]));
                }
            }
        }
        if (more) {
            buf ^= 1;
            sA[buf][lcol + 0][lrow] = na.x; sA[buf][lcol + 1][lrow] = na.y;
            sA[buf][lcol + 2][lrow] = na.z; sA[buf][lcol + 3][lrow] = na.w;
            sB[buf][lcol + 0][lrow] = nw.x; sB[buf][lcol + 1][lrow] = nw.y;
            sB[buf][lcol + 2][lrow] = nw.z; sB[buf][lcol + 3][lrow] = nw.w;
            __syncthreads();
        }
    }

    float acc[8][8];
#pragma unroll
    for (int i = 0; i < 8; i++)
#pragma unroll
        for (int jp = 0; jp < 4; jp++) {
            acc[i][2 * jp + 0] = __uint_as_float((uint32_t)(acc2[i][jp]));
            acc[i][2 * jp + 1] = __uint_as_float((uint32_t)(acc2[i][jp] >> 32));
        }

    float bs[8];
#pragma unroll
    for (int j = 0; j < 8; j++) {
        int n = bn + ((j < 4) ? (tx * 4 + j) : (64 + tx * 4 + (j - 4)));
        bs[j] = bias[n];
    }
#pragma unroll
    for (int i = 0; i < 8; i++) {
        int m = bm + ((i < 4) ? (ty * 4 + i) : (64 + ty * 4 + (i - 4)));
        float4 v0 = make_float4(acc[i][0] + bs[0], acc[i][1] + bs[1],
                                acc[i][2] + bs[2], acc[i][3] + bs[3]);
        float4 v1 = make_float4(acc[i][4] + bs[4], acc[i][5] + bs[5],
                                acc[i][6] + bs[6], acc[i][7] + bs[7]);
        *(float4*)&g_pre[(size_t)m * H_ + bn + tx * 4] = v0;
        *(float4*)&g_pre[(size_t)m * H_ + bn + 64 + tx * 4] = v1;
    }
}

// ---------------------------------------------------------------------------
// Kernel 2: ALIF recurrence over T per (b,h) with 32-deep load batches
// (32 independent loads in flight per thread), weighted partial reduce,
// and last-block finalize (out[b] = sum_c g_part[b*4+c] + b_out[0]).
// Recurrence math and all reduction orders unchanged from R12.
// ---------------------------------------------------------------------------
__global__ __launch_bounds__(256) void alif_scan_kernel(
    const float* __restrict__ W_out,
    const float* __restrict__ b_out,
    float* __restrict__ out)
{
    const int b  = blockIdx.x >> 2;
    const int hc = blockIdx.x & 3;
    const int h  = hc * 256 + threadIdx.x;

    const float* p = g_pre + (size_t)b * T_ * H_ + h;

    float mem = 0.0f, adapt = 0.0f, cnt = 0.0f;

    for (int t0 = 0; t0 < T_; t0 += 32) {
        float v[32];
#pragma unroll
        for (int q = 0; q < 32; q++)
            v[q] = p[(size_t)(t0 + q) * H_];
#pragma unroll
        for (int q = 0; q < 32; q++) {
            mem = 0.9f * mem + v[q] - adapt;
            float spk = (mem > 0.0f) ? 1.0f : 0.0f;
            adapt += 0.1f * spk;
            mem -= spk;
            cnt += spk;
        }
    }

    float val = cnt * (1.0f / (float)T_) * W_out[h];

    __shared__ float red[256];
    red[threadIdx.x] = val;
    __syncthreads();
#pragma unroll
    for (int s = 128; s > 0; s >>= 1) {
        if (threadIdx.x < s) red[threadIdx.x] += red[threadIdx.x + s];
        __syncthreads();
    }

    // Publish partial, then the last-arriving block finalizes the output.
    __shared__ int s_last;
    if (threadIdx.x == 0) {
        g_part[blockIdx.x] = red[0];
        __threadfence();
        int t = atomicAdd(&g_ticket, 1);
        s_last = (t == 255) ? 1 : 0;
    }
    __syncthreads();

    if (s_last) {
        __threadfence();   // acquire: order ticket read before g_part reads
        int bb = threadIdx.x;
        if (bb < B_) {
            float s = __ldcg(&g_part[bb * 4 + 0]) + __ldcg(&g_part[bb * 4 + 1]) +
                      __ldcg(&g_part[bb * 4 + 2]) + __ldcg(&g_part[bb * 4 + 3]);
            out[bb] = s + b_out[0];
        }
        if (threadIdx.x == 0) g_ticket = 0;   // clean state for graph replay
    }
}

extern "C" void kernel_launch(void* const* d_in, const int* in_sizes, int n_in,
                              void* d_out, int out_size)
{
    (void)in_sizes; (void)n_in; (void)out_size;
    const float* x     = (const float*)d_in[0];  // [64,256,512]
    const float* W_in  = (const float*)d_in[1];  // [1024,512]
    const float* b_in  = (const float*)d_in[2];  // [1024]
    const float* W_out = (const float*)d_in[3];  // [1,1024]
    const float* b_out = (const float*)d_in[4];  // [1]
    float* out = (float*)d_out;                  // [64,1]

    dim3 ggrid(H_ / BN, M_ / BM);                // (8, 128)
    gemm_bias_kernel<<<ggrid, 256>>>(x, W_in, b_in);
    alif_scan_kernel<<<256, 256>>>(W_out, b_out, out);
}